// round 10
// baseline (speedup 1.0000x reference)
#include <cuda_runtime.h>
#include <cuda_bf16.h>

#define N_NODES 100000
#define N_EDGES 6400000
#define F_IN 5
#define F_HID 5
#define F_OUT 10

// Scratch (allocation-free): padded feature rows (stride 8 floats = 32B, 16B-aligned)
__device__ __align__(16) float g_x8[N_NODES * 8];   // padded input features
__device__ __align__(16) float g_h8[N_NODES * 8];   // padded layer-1 activations
__device__ __align__(16) float g_agg[N_NODES * 8];  // atomic accumulator (reused both layers)
__device__ float g_deg[N_NODES];                    // in-degree (float)

__device__ __forceinline__ void red_add_v4(float* addr, float a, float b, float c, float d) {
    asm volatile("red.global.add.v4.f32 [%0], {%1,%2,%3,%4};"
                 :: "l"(addr), "f"(a), "f"(b), "f"(c), "f"(d) : "memory");
}

__device__ __forceinline__ float fast_sigmoid(float x) {
    return 1.0f / (1.0f + __expf(-x));
}

// Init: zero deg + agg, copy x into padded layout
__global__ __launch_bounds__(256) void init_kernel(const float* __restrict__ x) {
    int i = blockIdx.x * blockDim.x + threadIdx.x;
    if (i >= N_NODES) return;
    g_deg[i] = 0.0f;
    const float* xr = x + (size_t)i * F_IN;
    float4 v = make_float4(xr[0], xr[1], xr[2], xr[3]);
    *reinterpret_cast<float4*>(g_x8 + (size_t)i * 8) = v;
    g_x8[(size_t)i * 8 + 4] = xr[4];
    *reinterpret_cast<float4*>(g_agg + (size_t)i * 8) = make_float4(0.f, 0.f, 0.f, 0.f);
    g_agg[(size_t)i * 8 + 4] = 0.0f;
}

// Edge pass: gather feature row of src, RED into agg[dst]. Layer 1 also counts degree.
template <bool LAYER1>
__global__ __launch_bounds__(256) void edge_kernel(const int* __restrict__ src,
                                                   const int* __restrict__ dst) {
    int e = blockIdx.x * blockDim.x + threadIdx.x;
    if (e >= N_EDGES) return;
    int s = src[e];
    int d = dst[e];
    const float* feat = LAYER1 ? g_x8 : g_h8;
    const float4 v = *reinterpret_cast<const float4*>(feat + (size_t)s * 8);
    const float v4 = feat[(size_t)s * 8 + 4];
    float* ap = g_agg + (size_t)d * 8;
    red_add_v4(ap, v.x, v.y, v.z, v.w);
    atomicAdd(ap + 4, v4);
    if (LAYER1) atomicAdd(g_deg + d, 1.0f);
}

// Node epilogue layer 1: h = sigmoid(x@Ws + (agg/deg)@Wn + b); also re-zero agg.
__global__ __launch_bounds__(256) void node1_kernel(const float* __restrict__ Ws,
                                                    const float* __restrict__ Wn,
                                                    const float* __restrict__ b) {
    int v = blockIdx.x * blockDim.x + threadIdx.x;
    if (v >= N_NODES) return;
    float inv = 1.0f / fmaxf(g_deg[v], 1.0f);
    float xv[F_IN], av[F_IN];
#pragma unroll
    for (int f = 0; f < F_IN; f++) {
        xv[f] = g_x8[(size_t)v * 8 + f];
        av[f] = g_agg[(size_t)v * 8 + f] * inv;
    }
#pragma unroll
    for (int j = 0; j < F_HID; j++) {
        float acc = b[j];
#pragma unroll
        for (int f = 0; f < F_IN; f++) {
            acc = fmaf(xv[f], Ws[f * F_HID + j], acc);
            acc = fmaf(av[f], Wn[f * F_HID + j], acc);
        }
        g_h8[(size_t)v * 8 + j] = fast_sigmoid(acc);
    }
    // reset accumulator for layer 2
    *reinterpret_cast<float4*>(g_agg + (size_t)v * 8) = make_float4(0.f, 0.f, 0.f, 0.f);
    g_agg[(size_t)v * 8 + 4] = 0.0f;
}

// Node epilogue layer 2: out = sigmoid(h@Ws2 + (agg/deg)@Wn2 + b2)
__global__ __launch_bounds__(256) void node2_kernel(const float* __restrict__ Ws,
                                                    const float* __restrict__ Wn,
                                                    const float* __restrict__ b,
                                                    float* __restrict__ out) {
    int v = blockIdx.x * blockDim.x + threadIdx.x;
    if (v >= N_NODES) return;
    float inv = 1.0f / fmaxf(g_deg[v], 1.0f);
    float hv[F_HID], av[F_HID];
#pragma unroll
    for (int f = 0; f < F_HID; f++) {
        hv[f] = g_h8[(size_t)v * 8 + f];
        av[f] = g_agg[(size_t)v * 8 + f] * inv;
    }
#pragma unroll
    for (int j = 0; j < F_OUT; j++) {
        float acc = b[j];
#pragma unroll
        for (int f = 0; f < F_HID; f++) {
            acc = fmaf(hv[f], Ws[f * F_OUT + j], acc);
            acc = fmaf(av[f], Wn[f * F_OUT + j], acc);
        }
        out[(size_t)v * F_OUT + j] = fast_sigmoid(acc);
    }
}

extern "C" void kernel_launch(void* const* d_in, const int* in_sizes, int n_in,
                              void* d_out, int out_size) {
    const float* x   = (const float*)d_in[0];
    const int*   src = (const int*)d_in[1];
    const int*   dst = (const int*)d_in[2];
    const float* Ws1 = (const float*)d_in[3];
    const float* Wn1 = (const float*)d_in[4];
    const float* b1  = (const float*)d_in[5];
    const float* Ws2 = (const float*)d_in[6];
    const float* Wn2 = (const float*)d_in[7];
    const float* b2  = (const float*)d_in[8];
    float* out = (float*)d_out;

    const int nb_nodes = (N_NODES + 255) / 256;
    const int nb_edges = (N_EDGES + 255) / 256;

    init_kernel<<<nb_nodes, 256>>>(x);
    edge_kernel<true><<<nb_edges, 256>>>(src, dst);
    node1_kernel<<<nb_nodes, 256>>>(Ws1, Wn1, b1);
    edge_kernel<false><<<nb_edges, 256>>>(src, dst);
    node2_kernel<<<nb_nodes, 256>>>(Ws2, Wn2, b2, out);
}